// round 11
// baseline (speedup 1.0000x reference)
#include <cuda_runtime.h>

// Problem constants (from reference)
#define UPDATE_SIZE 4096
#define BATCH 256
#define NUM_UPD 16
#define SNAP_SIZE (UPDATE_SIZE * NUM_UPD)                   // 65536
#define OUT_SIZE (UPDATE_SIZE * BATCH)                      // 1048576
#define SNAP_LEN (SNAP_SIZE + (BATCH - 1) * UPDATE_SIZE)    // 1110016
#define SNAP_V4 (SNAP_LEN / 4)                              // 277504
#define ZERO_V4 (OUT_SIZE / 4)                              // 262144
#define V4_PER_BLK (UPDATE_SIZE / 4)                        // 1024
#define UPD_ROW_V4 (SNAP_SIZE / 4)                          // 16384
// float4 index in update for step i, snap block b, column r:
//   i*16384 + (b-i)*1024 + r = i*15360 + t
#define I_STRIDE_V4 (UPD_ROW_V4 - V4_PER_BLK)               // 15360
#define GRP 4
#define TPB 512
#define TOTAL_THREADS (SNAP_V4 + ZERO_V4)                   // 539648
#define NBLK ((TOTAL_THREADS + TPB - 1) / TPB)              // 1054

__global__ __launch_bounds__(TPB) void online_avg_kernel(
    const float4* __restrict__ upd,    // (256, 65536) as float4
    const float4* __restrict__ snap,   // (1110016,) as float4
    const float* __restrict__ idxp,    // (1,)
    float4* __restrict__ out4,
    float* __restrict__ out)
{
    int tt = blockIdx.x * TPB + threadIdx.x;

    // Zero-fill role FIRST in grid order: bids [0, 512) are pure-write CTAs,
    // draining the 4 MB write burst during startup instead of at the tail.
    if (tt < ZERO_V4) {
        out4[SNAP_V4 + tt] = make_float4(0.f, 0.f, 0.f, 0.f);
        if (tt == 0)
            out[OUT_SIZE + SNAP_LEN] = __ldg(idxp) + (float)BATCH;
        return;
    }
    int t = tt - ZERO_V4;            // snap position, 0 .. SNAP_V4-1
    if (t >= SNAP_V4) return;

    int b = t >> 10;                 // snap block index, 0..270
    float idx0 = __ldg(idxp);
    float4 s;

    if (b >= NUM_UPD - 1 && b < BATCH && idx0 >= 0.0f) {
        // FAST PATH (241/271 blocks): all 16 steps valid and wt == k+1
        // exactly, so the recurrence is a running mean -> output is the
        // arithmetic mean of the 16 loads. Pairwise tree sum (depth 4).
        const float4* p = upd + t + (b - (NUM_UPD - 1)) * I_STRIDE_V4;

        float4 acc[GRP];
        #pragma unroll
        for (int j = 0; j < GRP; ++j)
            acc[j] = p[j * I_STRIDE_V4];
        #pragma unroll
        for (int g = 1; g < NUM_UPD / GRP; ++g) {
            #pragma unroll
            for (int j = 0; j < GRP; ++j) {
                float4 x = p[(g * GRP + j) * I_STRIDE_V4];
                acc[j].x += x.x; acc[j].y += x.y;
                acc[j].z += x.z; acc[j].w += x.w;
            }
        }
        float4 a0, a1;
        a0.x = acc[0].x + acc[1].x;  a0.y = acc[0].y + acc[1].y;
        a0.z = acc[0].z + acc[1].z;  a0.w = acc[0].w + acc[1].w;
        a1.x = acc[2].x + acc[3].x;  a1.y = acc[2].y + acc[3].y;
        a1.z = acc[2].z + acc[3].z;  a1.w = acc[2].w + acc[3].w;
        const float inv = 1.0f / (float)NUM_UPD;
        s.x = (a0.x + a1.x) * inv;   s.y = (a0.y + a1.y) * inv;
        s.z = (a0.z + a1.z) * inv;   s.w = (a0.w + a1.w) * inv;
    } else {
        // GENERIC PATH: head (b<15), tail (b>255), or idx0 < 0.
        // Exact reference recurrence with clamped loads.
        bool need_snap = (b < NUM_UPD - 1) || (idx0 < 0.0f);
        s = need_snap ? snap[t] : make_float4(0.f, 0.f, 0.f, 0.f);

        #define ROW(k) \
            ( (b - (NUM_UPD - 1) + (k)) < 0 ? 0 : \
              ((b - (NUM_UPD - 1) + (k)) > (BATCH - 1) ? (BATCH - 1) : (b - (NUM_UPD - 1) + (k))) )

        float4 xa[GRP], xb[GRP];
        #pragma unroll
        for (int j = 0; j < GRP; ++j)
            xa[j] = upd[t + ROW(j) * I_STRIDE_V4];

        #pragma unroll
        for (int g = 0; g < NUM_UPD / GRP; ++g) {
            if (g < NUM_UPD / GRP - 1) {
                #pragma unroll
                for (int j = 0; j < GRP; ++j)
                    xb[j] = upd[t + ROW((g + 1) * GRP + j) * I_STRIDE_V4];
            }
            #pragma unroll
            for (int j = 0; j < GRP; ++j) {
                int k = g * GRP + j;
                int i = b - (NUM_UPD - 1) + k;
                bool valid = (i >= 0) && (i < BATCH);
                float wt = fminf((float)(k + 1), idx0 + (float)i + 1.0f);
                float rw = valid ? (1.0f / wt) : 0.0f;
                s.x = fmaf(xa[j].x - s.x, rw, s.x);
                s.y = fmaf(xa[j].y - s.y, rw, s.y);
                s.z = fmaf(xa[j].z - s.z, rw, s.z);
                s.w = fmaf(xa[j].w - s.w, rw, s.w);
            }
            #pragma unroll
            for (int j = 0; j < GRP; ++j) xa[j] = xb[j];
        }
        #undef ROW
    }

    // d_out[p] = snap_final[p] for p < SNAP_LEN covers both `output`
    // [0, OUT_SIZE) and new_snapshot's live prefix [OUT_SIZE, SNAP_LEN).
    out4[t] = s;
}

extern "C" void kernel_launch(void* const* d_in, const int* in_sizes, int n_in,
                              void* d_out, int out_size)
{
    const float4* upd  = (const float4*)d_in[0];
    const float4* snap = (const float4*)d_in[1];
    const float*  idxp = (const float*)d_in[2];

    float4* out4 = (float4*)d_out;
    float*  out  = (float*)d_out;

    online_avg_kernel<<<NBLK, TPB>>>(upd, snap, idxp, out4, out);
}

// round 12
// speedup vs baseline: 1.1134x; 1.1134x over previous
#include <cuda_runtime.h>

// Problem constants (from reference)
#define UPDATE_SIZE 4096
#define BATCH 256
#define NUM_UPD 16
#define SNAP_SIZE (UPDATE_SIZE * NUM_UPD)                   // 65536
#define OUT_SIZE (UPDATE_SIZE * BATCH)                      // 1048576
#define SNAP_LEN (SNAP_SIZE + (BATCH - 1) * UPDATE_SIZE)    // 1110016
#define SNAP_V4 (SNAP_LEN / 4)                              // 277504
#define ZERO_V4 (OUT_SIZE / 4)                              // 262144
#define V4_PER_BLK (UPDATE_SIZE / 4)                        // 1024
#define UPD_ROW_V4 (SNAP_SIZE / 4)                          // 16384
// float4 index in update for step i, snap block b, column r:
//   i*16384 + (b-i)*1024 + r = i*15360 + t
#define I_STRIDE_V4 (UPD_ROW_V4 - V4_PER_BLK)               // 15360
#define GRP 4

__global__ __launch_bounds__(256) void online_avg_kernel(
    const float4* __restrict__ upd,    // (256, 65536) as float4
    const float4* __restrict__ snap,   // (1110016,) as float4
    const float* __restrict__ idxp,    // (1,)
    float4* __restrict__ out4,
    float* __restrict__ out)
{
    int t = blockIdx.x * blockDim.x + threadIdx.x;   // grid covers exactly SNAP_V4

    // Fused zero-fill: every thread t < ZERO_V4 also owns one tail float4.
    if (t < ZERO_V4)
        __stcs(&out4[SNAP_V4 + t], make_float4(0.f, 0.f, 0.f, 0.f));
    if (t == 0)
        out[OUT_SIZE + SNAP_LEN] = __ldg(idxp) + (float)BATCH;

    int b = t >> 10;                 // snap block index, 0..270
    float idx0 = __ldg(idxp);
    float4 s;

    if (b >= NUM_UPD - 1 && b < BATCH && idx0 >= 0.0f) {
        // ---- FAST PATH (241/271 blocks): all 16 steps valid and
        // idx0 + i + 1 >= k+1 for every step, so wt == k+1 exactly ->
        // rw constant-folds; k==0 has rw=1 so s = x[0] (snapshot is dead).
        const float4* p = upd + t + (b - (NUM_UPD - 1)) * I_STRIDE_V4;

        float4 xa[GRP], xb[GRP];
        #pragma unroll
        for (int j = 0; j < GRP; ++j)
            xa[j] = __ldcs(p + j * I_STRIDE_V4);

        s = make_float4(0.f, 0.f, 0.f, 0.f);
        #pragma unroll
        for (int g = 0; g < NUM_UPD / GRP; ++g) {
            if (g < NUM_UPD / GRP - 1) {
                #pragma unroll
                for (int j = 0; j < GRP; ++j)
                    xb[j] = __ldcs(p + ((g + 1) * GRP + j) * I_STRIDE_V4);
            }
            #pragma unroll
            for (int j = 0; j < GRP; ++j) {
                int k = g * GRP + j;
                if (k == 0) {
                    s = xa[0];                      // weight-1 step overwrites
                } else {
                    float rw = 1.0f / (float)(k + 1);  // compile-time constant
                    s.x = fmaf(xa[j].x - s.x, rw, s.x);
                    s.y = fmaf(xa[j].y - s.y, rw, s.y);
                    s.z = fmaf(xa[j].z - s.z, rw, s.z);
                    s.w = fmaf(xa[j].w - s.w, rw, s.w);
                }
            }
            #pragma unroll
            for (int j = 0; j < GRP; ++j) xa[j] = xb[j];
        }
    } else {
        // ---- GENERIC PATH: head (b<15), tail (b>255), or idx0 < 0.
        bool need_snap = (b < NUM_UPD - 1) || (idx0 < 0.0f);
        s = need_snap ? snap[t] : make_float4(0.f, 0.f, 0.f, 0.f);

        #define ROW(k) \
            ( (b - (NUM_UPD - 1) + (k)) < 0 ? 0 : \
              ((b - (NUM_UPD - 1) + (k)) > (BATCH - 1) ? (BATCH - 1) : (b - (NUM_UPD - 1) + (k))) )

        float4 xa[GRP], xb[GRP];
        #pragma unroll
        for (int j = 0; j < GRP; ++j)
            xa[j] = __ldcs(&upd[t + ROW(j) * I_STRIDE_V4]);

        #pragma unroll
        for (int g = 0; g < NUM_UPD / GRP; ++g) {
            if (g < NUM_UPD / GRP - 1) {
                #pragma unroll
                for (int j = 0; j < GRP; ++j)
                    xb[j] = __ldcs(&upd[t + ROW((g + 1) * GRP + j) * I_STRIDE_V4]);
            }
            #pragma unroll
            for (int j = 0; j < GRP; ++j) {
                int k = g * GRP + j;
                int i = b - (NUM_UPD - 1) + k;
                bool valid = (i >= 0) && (i < BATCH);
                float wt = fminf((float)(k + 1), idx0 + (float)i + 1.0f);
                float rw = valid ? (1.0f / wt) : 0.0f;
                s.x = fmaf(xa[j].x - s.x, rw, s.x);
                s.y = fmaf(xa[j].y - s.y, rw, s.y);
                s.z = fmaf(xa[j].z - s.z, rw, s.z);
                s.w = fmaf(xa[j].w - s.w, rw, s.w);
            }
            #pragma unroll
            for (int j = 0; j < GRP; ++j) xa[j] = xb[j];
        }
        #undef ROW
    }

    // d_out[p] = snap_final[p] for p < SNAP_LEN covers both `output`
    // [0, OUT_SIZE) and new_snapshot's live prefix [OUT_SIZE, SNAP_LEN).
    __stcs(&out4[t], s);
}

extern "C" void kernel_launch(void* const* d_in, const int* in_sizes, int n_in,
                              void* d_out, int out_size)
{
    const float4* upd  = (const float4*)d_in[0];
    const float4* snap = (const float4*)d_in[1];
    const float*  idxp = (const float*)d_in[2];

    float4* out4 = (float4*)d_out;
    float*  out  = (float*)d_out;

    const int threads = 256;
    const int blocks = SNAP_V4 / threads;   // 1084 exactly (277504 = 1084*256)

    online_avg_kernel<<<blocks, threads>>>(upd, snap, idxp, out4, out);
}